// round 2
// baseline (speedup 1.0000x reference)
#include <cuda_runtime.h>

#define BS 64
#define DX 512
#define DY 512
#define LTOT (DX * DY)            /* 262144 */
#define CHUNK 1024
#define NCHUNK (LTOT / CHUNK)     /* 256 */
#define TPB 256

// scratch (no allocations allowed)
__device__ int g_counts[BS * NCHUNK];
__device__ int g_offsets[BS * NCHUNK];
__device__ int g_lens[BS];

// ---------------------------------------------------------------------------
// block-wide exclusive scan over 256 threads (cnt <= 4 each)
// ---------------------------------------------------------------------------
__device__ __forceinline__ int block_excl_scan256(int cnt, int t, int* warp_tot) {
    int lane = t & 31, w = t >> 5;
    int v = cnt;
#pragma unroll
    for (int o = 1; o < 32; o <<= 1) {
        int u = __shfl_up_sync(0xffffffffu, v, o);
        if (lane >= o) v += u;
    }
    if (lane == 31) warp_tot[w] = v;
    __syncthreads();
    if (t < 8) {
        int x = warp_tot[t];
#pragma unroll
        for (int o = 1; o < 8; o <<= 1) {
            int u = __shfl_up_sync(0x000000ffu, x, o);
            if (t >= o) x += u;
        }
        warp_tot[t] = x;
    }
    __syncthreads();
    int base = (w > 0) ? warp_tot[w - 1] : 0;
    return base + v - cnt;   // exclusive prefix for this thread
}

// ---------------------------------------------------------------------------
// Kernel 1: per-chunk nonzero counts
// ---------------------------------------------------------------------------
__global__ void k_count(const float* __restrict__ hist) {
    int b = blockIdx.y, c = blockIdx.x, t = threadIdx.x;
    const float4* p = reinterpret_cast<const float4*>(hist + (size_t)b * LTOT);
    float4 v = p[c * TPB + t];
    int cnt = (v.x != 0.f) + (v.y != 0.f) + (v.z != 0.f) + (v.w != 0.f);
#pragma unroll
    for (int o = 16; o; o >>= 1) cnt += __shfl_down_sync(0xffffffffu, cnt, o);
    __shared__ int ws[8];
    if ((t & 31) == 0) ws[t >> 5] = cnt;
    __syncthreads();
    if (t == 0) {
        int s = 0;
#pragma unroll
        for (int i = 0; i < 8; i++) s += ws[i];
        g_counts[b * NCHUNK + c] = s;
    }
}

// ---------------------------------------------------------------------------
// Kernel 2: per-batch exclusive scan of 256 chunk counts -> offsets + lens
// ---------------------------------------------------------------------------
__global__ void k_scan(float* __restrict__ out_lens) {
    int b = blockIdx.x, t = threadIdx.x;
    __shared__ int warp_tot[8];
    int cnt = g_counts[b * NCHUNK + t];
    int excl = block_excl_scan256(cnt, t, warp_tot);
    g_offsets[b * NCHUNK + t] = excl;
    if (t == NCHUNK - 1) {
        int total = excl + cnt;
        g_lens[b] = total;
        out_lens[b] = (float)total;
    }
}

// ---------------------------------------------------------------------------
// Kernel 3: compacted write of (x, y) + w
// ---------------------------------------------------------------------------
__global__ void k_write(const float* __restrict__ hist,
                        const float* __restrict__ x_lims,
                        const float* __restrict__ y_lims,
                        float* __restrict__ out) {
    int b = blockIdx.y, c = blockIdx.x, t = threadIdx.x;
    const float4* p = reinterpret_cast<const float4*>(hist + (size_t)b * LTOT);
    float4 v = p[c * TPB + t];

    int m0 = (v.x != 0.f), m1 = (v.y != 0.f), m2 = (v.z != 0.f), m3 = (v.w != 0.f);
    int cnt = m0 + m1 + m2 + m3;

    __shared__ int warp_tot[8];
    int excl = block_excl_scan256(cnt, t, warp_tot);
    int pos = g_offsets[b * NCHUNK + c] + excl;

    float x0 = x_lims[2 * b], x1 = x_lims[2 * b + 1];
    float y0 = y_lims[2 * b], y1 = y_lims[2 * b + 1];
    float cxw = (x1 - x0) / (float)DX;
    float cyw = (y1 - y0) / (float)DY;
    float xoff = x0 + 0.5f * cxw;
    float yoff = y0 + 0.5f * cyw;

    float2* pc = reinterpret_cast<float2*>(out) + (size_t)b * LTOT;   // [L] of (x,y)
    float* wv  = out + (size_t)BS * LTOT * 2 + (size_t)b * LTOT;      // [L]

    int elem = c * CHUNK + t * 4;
    float vals[4] = {v.x, v.y, v.z, v.w};
#pragma unroll
    for (int k = 0; k < 4; k++) {
        if (vals[k] != 0.f) {
            int e = elem + k;
            int i = e >> 9;        // row (x index)
            int j = e & (DY - 1);  // col (y index)
            float x = xoff + (float)i * cxw;
            float y = yoff + (float)j * cyw;
            pc[pos] = make_float2(x, y);
            wv[pos] = vals[k];
            pos++;
        }
    }
}

// ---------------------------------------------------------------------------
// Kernel 4: zero the ragged tail [lens[b], L)
// ---------------------------------------------------------------------------
__global__ void k_zerotail(float* __restrict__ out) {
    int b = blockIdx.y;
    int len = g_lens[b];
    int p = (blockIdx.x * TPB + threadIdx.x) * 4;   // 4 output positions / thread
    if (p + 3 < len) return;

    float* pcb = out + (size_t)b * LTOT * 2;
    float* wb  = out + (size_t)BS * LTOT * 2 + (size_t)b * LTOT;

    if (p >= len) {
        float4 z = make_float4(0.f, 0.f, 0.f, 0.f);
        reinterpret_cast<float4*>(pcb)[(p >> 1)]     = z;  // floats [2p, 2p+4)
        reinterpret_cast<float4*>(pcb)[(p >> 1) + 1] = z;  // floats [2p+4, 2p+8)
        reinterpret_cast<float4*>(wb)[p >> 2]        = z;
    } else {
#pragma unroll
        for (int k = 0; k < 4; k++) {
            int q = p + k;
            if (q >= len) {
                pcb[2 * q]     = 0.f;
                pcb[2 * q + 1] = 0.f;
                wb[q]          = 0.f;
            }
        }
    }
}

// ---------------------------------------------------------------------------
// launch
// ---------------------------------------------------------------------------
extern "C" void kernel_launch(void* const* d_in, const int* in_sizes, int n_in,
                              void* d_out, int out_size) {
    const float* hist   = (const float*)d_in[0];
    const float* x_lims = (const float*)d_in[1];
    const float* y_lims = (const float*)d_in[2];
    float* out = (float*)d_out;
    float* out_lens = out + (size_t)BS * LTOT * 3;

    dim3 gridA(NCHUNK, BS);
    k_count<<<gridA, TPB>>>(hist);
    k_scan<<<BS, NCHUNK>>>(out_lens);
    k_write<<<gridA, TPB>>>(hist, x_lims, y_lims, out);
    dim3 gridD(LTOT / (TPB * 4), BS);
    k_zerotail<<<gridD, TPB>>>(out);
}

// round 3
// speedup vs baseline: 1.0433x; 1.0433x over previous
#include <cuda_runtime.h>

#define BS 64
#define DX 512
#define DY 512
#define LTOT (DX * DY)            /* 262144 */
#define CHUNK 1024
#define NCHUNK (LTOT / CHUNK)     /* 256 */
#define TPB 256
#define VMASK 0x3FFFFFFFu

// decoupled-lookback state, one word per (batch, chunk):
//   bits[31:30] flag: 0 = invalid, 1 = aggregate, 2 = inclusive prefix
//   bits[29:0]  value
__device__ unsigned g_state[BS * NCHUNK];

__global__ void __launch_bounds__(TPB)
k_fused(const float* __restrict__ hist,
        const float* __restrict__ x_lims,
        const float* __restrict__ y_lims,
        float* __restrict__ out) {
    const int b = blockIdx.y, c = blockIdx.x, t = threadIdx.x;
    const int lane = t & 31, w = t >> 5;

    // ---- load 4 floats / thread (coalesced float4) ----
    const float4* p = reinterpret_cast<const float4*>(hist + (size_t)b * LTOT);
    float4 v = p[c * TPB + t];
    int cnt = (v.x != 0.f) + (v.y != 0.f) + (v.z != 0.f) + (v.w != 0.f);

    // ---- block-wide exclusive scan of per-thread counts ----
    __shared__ int warp_tot[8];
    __shared__ int s_prefix;
    int inc = cnt;
#pragma unroll
    for (int o = 1; o < 32; o <<= 1) {
        int u = __shfl_up_sync(0xffffffffu, inc, o);
        if (lane >= o) inc += u;
    }
    if (lane == 31) warp_tot[w] = inc;
    __syncthreads();
    if (t < 8) {
        int x = warp_tot[t];
#pragma unroll
        for (int o = 1; o < 8; o <<= 1) {
            int u = __shfl_up_sync(0x000000ffu, x, o);
            if (t >= o) x += u;
        }
        warp_tot[t] = x;
    }
    __syncthreads();
    int excl = ((w > 0) ? warp_tot[w - 1] : 0) + inc - cnt;  // exclusive thread prefix
    int total = warp_tot[7];                                  // block total

    // ---- publish aggregate (block 0 publishes inclusive directly) ----
    unsigned* st = g_state + b * NCHUNK;
    if (t == 0) {
        unsigned flag = (c == 0) ? 2u : 1u;
        atomicExch(&st[c], (flag << 30) | (unsigned)total);
        if (c == 0) s_prefix = 0;
    }

    // ---- warp-parallel decoupled lookback (warp 0) ----
    if (w == 0 && c > 0) {
        int prefix = 0;
        int look = c;  // window is [look-32, look)
        for (;;) {
            int idx = look - 32 + lane;
            unsigned s = 0;
            if (idx >= 0) {
                s = *(volatile unsigned*)&st[idx];
                while ((s >> 30) == 0u) {
                    __nanosleep(40);
                    s = *(volatile unsigned*)&st[idx];
                }
            }
            unsigned bal = __ballot_sync(0xffffffffu, (s >> 30) == 2u);
            if (bal) {
                int hi = 31 - __clz(bal);  // highest lane holding an inclusive prefix
                int contrib = (lane >= hi) ? (int)(s & VMASK) : 0;
                prefix += __reduce_add_sync(0xffffffffu, contrib);
                break;
            }
            prefix += __reduce_add_sync(0xffffffffu, (int)(s & VMASK));
            look -= 32;
        }
        if (lane == 0) {
            atomicExch(&st[c], (2u << 30) | (unsigned)(prefix + total));
            s_prefix = prefix;
        }
    }
    __syncthreads();
    const int chunk_prefix = s_prefix;

    // ---- per-batch grid params ----
    float x0 = x_lims[2 * b], x1 = x_lims[2 * b + 1];
    float y0 = y_lims[2 * b], y1 = y_lims[2 * b + 1];
    float cxw = (x1 - x0) / (float)DX;
    float cyw = (y1 - y0) / (float)DY;
    float xoff = x0 + 0.5f * cxw;
    float yoff = y0 + 0.5f * cyw;

    float2* pc = reinterpret_cast<float2*>(out) + (size_t)b * LTOT;  // [L] of (x,y)
    float* wv  = out + (size_t)BS * LTOT * 2 + (size_t)b * LTOT;     // [L]

    // ---- compacted writes ----
    int pos = chunk_prefix + excl;
    int elem = c * CHUNK + t * 4;
    float vals[4] = {v.x, v.y, v.z, v.w};
#pragma unroll
    for (int k = 0; k < 4; k++) {
        if (vals[k] != 0.f) {
            int e = elem + k;
            int i = e >> 9;        // row (x index)
            int j = e & (DY - 1);  // col (y index)
            pc[pos] = make_float2(xoff + (float)i * cxw, yoff + (float)j * cyw);
            wv[pos] = vals[k];
            pos++;
        }
    }

    // ---- fused zero tail: this chunk's zeros, placed from the top down ----
    // zeros before this chunk = c*CHUNK - chunk_prefix; zeros here = CHUNK - total.
    // Regions tile [len, L) exactly with no overlap and no knowledge of len.
    int zoff = c * CHUNK - chunk_prefix;
    int zcnt = CHUNK - total;
    int zstart = LTOT - zoff - zcnt;
    for (int q = zstart + t; q < zstart + zcnt; q += TPB) {
        pc[q] = make_float2(0.f, 0.f);
        wv[q] = 0.f;
    }

    // ---- lens ----
    if (c == NCHUNK - 1 && t == 0)
        out[(size_t)BS * LTOT * 3 + b] = (float)(chunk_prefix + total);
}

// ---------------------------------------------------------------------------
// launch: memset state (graph memset node) + one fused kernel
// ---------------------------------------------------------------------------
extern "C" void kernel_launch(void* const* d_in, const int* in_sizes, int n_in,
                              void* d_out, int out_size) {
    const float* hist   = (const float*)d_in[0];
    const float* x_lims = (const float*)d_in[1];
    const float* y_lims = (const float*)d_in[2];
    float* out = (float*)d_out;

    static void* state_ptr = nullptr;
    if (!state_ptr) cudaGetSymbolAddress(&state_ptr, g_state);
    cudaMemsetAsync(state_ptr, 0, sizeof(unsigned) * BS * NCHUNK);

    dim3 grid(NCHUNK, BS);
    k_fused<<<grid, TPB>>>(hist, x_lims, y_lims, out);
}